// round 2
// baseline (speedup 1.0000x reference)
#include <cuda_runtime.h>

// ---------------- problem constants ----------------
#define NB 1024   // batch
#define NT 128    // timesteps
#define ND 256    // d_in
#define NH 128    // hidden == memory units == memory width
#define NG 512    // 4*NH gates
#define NK 640    // 128 (hh) + 512 (rv via A_q)

// ---------------- device scratch ----------------
__device__ float g_pre[(size_t)NT * NB * NG];   // [t][b][g] pre-activations (x·Wx + bias (+const0 at t=0))
__device__ float g_Wro[NG * NK];                // reordered weights: row rr=4u+gate, cols [W_hh | A_0..A_3]
__device__ float g_memsm[NH * NH];              // softmax(memory, axis=0)  [m][w]
__device__ float g_fA[2 * NK];                  // folded fc weights: [o][ fc_h(128) | fA_0..fA_3 ]
__device__ float g_hA[NB * NH];
__device__ float g_hB[NB * NH];
__device__ float g_c[NB * NH];
__device__ float g_hsum[NB * NH];
__device__ float g_bias[NG];
__device__ float g_const0[NG];

// ---------------- setup: softmax, bias, rv0 constant ----------------
__global__ void setup_kernel(const float* __restrict__ memory,
                             const float* __restrict__ b_ih,
                             const float* __restrict__ b_hh,
                             const float* __restrict__ rv0,
                             const float* __restrict__ W_ih) {
    int tid = threadIdx.x;  // 0..127 -> one column w of memory
    float mx = -1e30f;
    for (int m = 0; m < NH; m++) mx = fmaxf(mx, memory[m * NH + tid]);
    float s = 0.f;
    for (int m = 0; m < NH; m++) s += expf(memory[m * NH + tid] - mx);
    float inv = 1.f / s;
    for (int m = 0; m < NH; m++)
        g_memsm[m * NH + tid] = expf(memory[m * NH + tid] - mx) * inv;

    for (int g = tid; g < NG; g += 128) {
        g_bias[g] = b_ih[g] + b_hh[g];
        float c0 = 0.f;
        const float* w = W_ih + (size_t)g * 768 + 256;
        for (int k = 0; k < 512; k++) c0 += rv0[k] * w[k];
        g_const0[g] = c0;
    }
}

// ---------------- fold mem_sm into W_ih (A_q) and fc_w (fA_q) ----------------
// Wro row rr = 4*u + gate   (gate: 0=i,1=f,2=g,3=o; original g = gate*128+u)
__global__ void buildA_kernel(const float* __restrict__ W_ih,
                              const float* __restrict__ W_hh,
                              const float* __restrict__ fc_w) {
    int row = blockIdx.x;   // 0..513 (512,513 -> fc rows)
    int q   = blockIdx.y;   // 0..4 (0 = direct copy region)
    int j   = threadIdx.x;  // 0..127
    if (row < NG) {
        int u = row >> 2, gate = row & 3;
        int go = gate * 128 + u;
        if (q == 0) {
            g_Wro[(size_t)row * NK + j] = W_hh[(size_t)go * NH + j];
        } else {
            const float* w = W_ih + (size_t)go * 768 + 256 + (q - 1) * 128;
            float s = 0.f;
            for (int m = 0; m < NH; m++) s += w[m] * g_memsm[m * NH + j];
            g_Wro[(size_t)row * NK + q * 128 + j] = s;
        }
    } else {
        int o = row - NG;
        if (q == 0) {
            g_fA[o * NK + j] = fc_w[o * NK + j];
        } else {
            const float* w = fc_w + o * NK + 128 + (q - 1) * 128;
            float s = 0.f;
            for (int m = 0; m < NH; m++) s += w[m] * g_memsm[m * NH + j];
            g_fA[o * NK + q * 128 + j] = s;
        }
    }
}

// ---------------- pre: [NT*NB, 256] x [256, 512] GEMM (time-parallel) ----------------
__global__ __launch_bounds__(256)
void pre_kernel(const float* __restrict__ x, const float* __restrict__ W_ih) {
    __shared__ float As[32][68];
    __shared__ float Bs[32][68];
    int r0 = blockIdx.x * 64;     // output rows r = t*1024 + b
    int g0 = blockIdx.y * 64;     // gate columns
    int tid = threadIdx.x;
    int tx = tid & 15, ty = tid >> 4;
    float acc[4][4] = {};

    for (int k0 = 0; k0 < ND; k0 += 32) {
        #pragma unroll
        for (int i = 0; i < 8; i++) {
            int e = i * 256 + tid;
            int kk = e & 31, rl = e >> 5;
            int r = r0 + rl;
            int b = r & 1023, t = r >> 10;
            As[kk][rl] = x[((size_t)(b * NT + t)) * ND + k0 + kk];
        }
        #pragma unroll
        for (int i = 0; i < 8; i++) {
            int e = i * 256 + tid;
            int kk = e & 31, gl = e >> 5;
            Bs[kk][gl] = W_ih[(size_t)(g0 + gl) * 768 + k0 + kk];
        }
        __syncthreads();
        #pragma unroll
        for (int kk = 0; kk < 32; kk++) {
            float a[4], bb[4];
            #pragma unroll
            for (int i = 0; i < 4; i++) a[i] = As[kk][ty * 4 + i];
            #pragma unroll
            for (int j = 0; j < 4; j++) bb[j] = Bs[kk][tx * 4 + j];
            #pragma unroll
            for (int i = 0; i < 4; i++)
                #pragma unroll
                for (int j = 0; j < 4; j++) acc[i][j] += a[i] * bb[j];
        }
        __syncthreads();
    }

    int t = (r0 + ty * 4) >> 10;  // whole 64-row tile has the same t
    #pragma unroll
    for (int i = 0; i < 4; i++) {
        int r = r0 + ty * 4 + i;
        size_t base = (size_t)r * NG;
        #pragma unroll
        for (int j = 0; j < 4; j++) {
            int g = g0 + tx * 4 + j;
            float v = acc[i][j] + g_bias[g];
            if (t == 0) v += g_const0[g];
            g_pre[base + g] = v;
        }
    }
}

// ---------------- init ----------------
__global__ void init_kernel() {
    int i = blockIdx.x * blockDim.x + threadIdx.x;
    if (i < NB * NH) { g_hA[i] = 0.f; g_c[i] = 0.f; g_hsum[i] = 0.f; }
}

// ---------------- one recurrent step: GEMM (gathered rows) + LSTM pointwise ----------------
__global__ __launch_bounds__(256)
void step_kernel(int t) {
    const float* __restrict__ Hp = (t & 1) ? g_hB : g_hA;
    float* __restrict__ Hn = (t & 1) ? g_hA : g_hB;

    __shared__ float As[32][68];
    __shared__ float Bs[32][68];
    int b0  = blockIdx.x * 64;   // batch tile
    int rr0 = blockIdx.y * 64;   // reordered gate-row tile (16 units x 4 gates)
    int tid = threadIdx.x;
    int tx = tid & 15, ty = tid >> 4;
    float acc[4][4] = {};

    for (int k0 = 0; k0 < NK; k0 += 32) {
        #pragma unroll
        for (int i = 0; i < 8; i++) {
            int e = i * 256 + tid;
            int kk = e & 31, bl = e >> 5;
            int b = b0 + bl;
            int src, col;
            if (k0 < 128) { src = b; col = k0 + kk; }
            else {
                int q = (k0 - 128) >> 7;
                src = (4 * b + q) & 1023;          // batch-mixing gather
                col = ((k0 - 128) & 127) + kk;
            }
            As[kk][bl] = Hp[src * NH + col];
        }
        #pragma unroll
        for (int i = 0; i < 8; i++) {
            int e = i * 256 + tid;
            int kk = e & 31, rl = e >> 5;
            Bs[kk][rl] = g_Wro[(size_t)(rr0 + rl) * NK + k0 + kk];
        }
        __syncthreads();
        #pragma unroll
        for (int kk = 0; kk < 32; kk++) {
            float a[4], bb[4];
            #pragma unroll
            for (int i = 0; i < 4; i++) a[i] = As[kk][ty * 4 + i];
            #pragma unroll
            for (int j = 0; j < 4; j++) bb[j] = Bs[kk][tx * 4 + j];
            #pragma unroll
            for (int i = 0; i < 4; i++)
                #pragma unroll
                for (int j = 0; j < 4; j++) acc[i][j] += a[i] * bb[j];
        }
        __syncthreads();
    }

    // LSTM pointwise: thread owns unit u for 4 batches, all 4 gates (j = gate)
    int u = (rr0 >> 2) + tx;
    #pragma unroll
    for (int i = 0; i < 4; i++) {
        int b = b0 + ty * 4 + i;
        size_t pb = ((size_t)t * NB + b) * NG;
        float gi = acc[i][0] + g_pre[pb + u];
        float gf = acc[i][1] + g_pre[pb + 128 + u];
        float gg = acc[i][2] + g_pre[pb + 256 + u];
        float go = acc[i][3] + g_pre[pb + 384 + u];
        float si = 1.f / (1.f + expf(-gi));
        float sf = 1.f / (1.f + expf(-gf));
        float so = 1.f / (1.f + expf(-go));
        float tg = tanhf(gg);
        int idx = b * NH + u;
        float c = sf * g_c[idx] + si * tg;
        g_c[idx] = c;
        float h = so * tanhf(c);
        Hn[idx] = h;
        g_hsum[idx] += h;
    }
}

// ---------------- final: out = fc applied to mean-h with the same gather ----------------
__global__ void final_kernel(float* __restrict__ out, const float* __restrict__ fc_b) {
    int b = blockIdx.x * blockDim.x + threadIdx.x;
    if (b >= NB) return;
    #pragma unroll
    for (int o = 0; o < 2; o++) {
        const float* f = g_fA + o * NK;
        const float* hs = g_hsum + b * NH;
        float s = 0.f;
        for (int k = 0; k < NH; k++) s += f[k] * hs[k];
        #pragma unroll
        for (int q = 0; q < 4; q++) {
            const float* hq = g_hsum + ((4 * b + q) & 1023) * NH;
            const float* fq = f + 128 + q * 128;
            for (int m = 0; m < NH; m++) s += fq[m] * hq[m];
        }
        out[b * 2 + o] = fc_b[o] + s * (1.f / (float)NT);
    }
}

// ---------------- launch ----------------
extern "C" void kernel_launch(void* const* d_in, const int* in_sizes, int n_in,
                              void* d_out, int out_size) {
    const float* x      = (const float*)d_in[0];
    const float* memory = (const float*)d_in[1];
    const float* rv0    = (const float*)d_in[2];
    const float* W_ih   = (const float*)d_in[3];
    const float* W_hh   = (const float*)d_in[4];
    const float* b_ih   = (const float*)d_in[5];
    const float* b_hh   = (const float*)d_in[6];
    const float* fc_w   = (const float*)d_in[7];
    const float* fc_b   = (const float*)d_in[8];
    float* out = (float*)d_out;

    setup_kernel<<<1, 128>>>(memory, b_ih, b_hh, rv0, W_ih);
    buildA_kernel<<<dim3(514, 5), 128>>>(W_ih, W_hh, fc_w);
    pre_kernel<<<dim3((NT * NB) / 64, NG / 64), 256>>>(x, W_ih);
    init_kernel<<<dim3((NB * NH + 255) / 256), 256>>>();
    for (int t = 0; t < NT; t++)
        step_kernel<<<dim3(NB / 64, NG / 64), 256>>>(t);
    final_kernel<<<dim3(4), 256>>>(out, fc_b);
}

// round 3
// speedup vs baseline: 1.1834x; 1.1834x over previous
#include <cuda_runtime.h>

// ---------------- problem constants ----------------
#define NB 1024   // batch
#define NT 128    // timesteps
#define ND 256    // d_in
#define NH 128    // hidden == memory units == memory width
#define NG 512    // 4*NH gates
#define NK 640    // 128 (hh) + 512 (rv via A_q)

typedef unsigned long long ull;

// ---------------- f32x2 packed math ----------------
__device__ __forceinline__ ull ffma2(ull a, ull b, ull c) {
    ull d;
    asm("fma.rn.f32x2 %0, %1, %2, %3;" : "=l"(d) : "l"(a), "l"(b), "l"(c));
    return d;
}
__device__ __forceinline__ ull pack2(float lo, float hi) {
    ull d; asm("mov.b64 %0, {%1, %2};" : "=l"(d) : "f"(lo), "f"(hi)); return d;
}
__device__ __forceinline__ float2 unpack2(ull v) {
    float2 r; asm("mov.b64 {%0, %1}, %2;" : "=f"(r.x), "=f"(r.y) : "l"(v)); return r;
}

// bank-skewed base offset (floats) of duplicated column-group g (cols 4g..4g+3)
__device__ __forceinline__ int bso(int g) { return g * 8 + (g >> 2) * 4; }
#define BSD_STRIDE 144   // floats per kk row (max used = 140)

// ---------------- device scratch ----------------
__device__ float g_pre[(size_t)NT * NB * NG];   // [t*NB+b][g] pre-activations
__device__ float g_Wro[NG * NK];                // reordered: row rr=4u+gate, cols [W_hh | A_0..A_3]
__device__ float g_memsm[NH * NH];              // softmax(memory, axis=0)
__device__ float g_fA[2 * NK];                  // folded fc weights
__device__ float g_hA[NB * NH];
__device__ float g_hB[NB * NH];
__device__ float g_c[NB * NH];
__device__ float g_hsum[NB * NH];
__device__ float g_bias[NG];
__device__ float g_const0[NG];

// ---------------- setup: softmax, bias, rv0 constant ----------------
__global__ void setup_kernel(const float* __restrict__ memory,
                             const float* __restrict__ b_ih,
                             const float* __restrict__ b_hh,
                             const float* __restrict__ rv0,
                             const float* __restrict__ W_ih) {
    int tid = threadIdx.x;  // 0..127 -> one column w
    float mx = -1e30f;
    for (int m = 0; m < NH; m++) mx = fmaxf(mx, memory[m * NH + tid]);
    float s = 0.f;
    for (int m = 0; m < NH; m++) s += expf(memory[m * NH + tid] - mx);
    float inv = 1.f / s;
    for (int m = 0; m < NH; m++)
        g_memsm[m * NH + tid] = expf(memory[m * NH + tid] - mx) * inv;

    for (int g = tid; g < NG; g += 128) {
        g_bias[g] = b_ih[g] + b_hh[g];
        float c0 = 0.f;
        const float* w = W_ih + (size_t)g * 768 + 256;
        for (int k = 0; k < 512; k++) c0 += rv0[k] * w[k];
        g_const0[g] = c0;
    }
}

// ---------------- fold mem_sm into W_ih (A_q) and fc_w ----------------
__global__ void buildA_kernel(const float* __restrict__ W_ih,
                              const float* __restrict__ W_hh,
                              const float* __restrict__ fc_w) {
    int row = blockIdx.x;   // 0..513 (512,513 -> fc rows)
    int q   = blockIdx.y;   // 0..4 (0 = direct copy region)
    int j   = threadIdx.x;  // 0..127
    if (row < NG) {
        int u = row >> 2, gate = row & 3;
        int go = gate * 128 + u;
        if (q == 0) {
            g_Wro[(size_t)row * NK + j] = W_hh[(size_t)go * NH + j];
        } else {
            const float* w = W_ih + (size_t)go * 768 + 256 + (q - 1) * 128;
            float s = 0.f;
            for (int m = 0; m < NH; m++) s += w[m] * g_memsm[m * NH + j];
            g_Wro[(size_t)row * NK + q * 128 + j] = s;
        }
    } else {
        int o = row - NG;
        if (q == 0) {
            g_fA[o * NK + j] = fc_w[o * NK + j];
        } else {
            const float* w = fc_w + o * NK + 128 + (q - 1) * 128;
            float s = 0.f;
            for (int m = 0; m < NH; m++) s += w[m] * g_memsm[m * NH + j];
            g_fA[o * NK + q * 128 + j] = s;
        }
    }
}

// ---------------- shared GEMM body helpers ----------------
// smem: As [32][64] floats (row=kk, col=local output-row)
//       Bsd [32][BSD_STRIDE] floats, column c stored duplicated at bso(c>>2)+(c&3)*2
// thread (tx=tid&15, ty=tid>>4) accumulates rows ty*4..ty*4+3, cols tx*4..tx*4+3
// acc[ih][j]: packed rows (ty*4+2ih, ty*4+2ih+1), col tx*4+j

#define GEMM_COMPUTE(As, Bsd, acc, tx, ty)                                      \
    _Pragma("unroll")                                                           \
    for (int kk = 0; kk < 32; kk++) {                                           \
        ulonglong2 ap = *(const ulonglong2*)(As + kk * 64 + ty * 4);            \
        ulonglong2 b01 = *(const ulonglong2*)(Bsd + kk * BSD_STRIDE + bso(tx)); \
        ulonglong2 b23 = *(const ulonglong2*)(Bsd + kk * BSD_STRIDE + bso(tx) + 4); \
        acc[0][0] = ffma2(ap.x, b01.x, acc[0][0]);                              \
        acc[0][1] = ffma2(ap.x, b01.y, acc[0][1]);                              \
        acc[0][2] = ffma2(ap.x, b23.x, acc[0][2]);                              \
        acc[0][3] = ffma2(ap.x, b23.y, acc[0][3]);                              \
        acc[1][0] = ffma2(ap.y, b01.x, acc[1][0]);                              \
        acc[1][1] = ffma2(ap.y, b01.y, acc[1][1]);                              \
        acc[1][2] = ffma2(ap.y, b23.x, acc[1][2]);                              \
        acc[1][3] = ffma2(ap.y, b23.y, acc[1][3]);                              \
    }

#define STORE_TILES(As, Bsd, lane, kg, a0, a1, w0, w1)                          \
    {                                                                           \
        int r = kg * 8;                                                         \
        As[(r+0)*64+lane]=a0.x; As[(r+1)*64+lane]=a0.y;                         \
        As[(r+2)*64+lane]=a0.z; As[(r+3)*64+lane]=a0.w;                         \
        As[(r+4)*64+lane]=a1.x; As[(r+5)*64+lane]=a1.y;                         \
        As[(r+6)*64+lane]=a1.z; As[(r+7)*64+lane]=a1.w;                         \
        ull* B64 = (ull*)Bsd;                                                   \
        int posU = (bso(lane >> 2) >> 1) + (lane & 3);                          \
        B64[(r+0)*(BSD_STRIDE/2)+posU] = pack2(w0.x, w0.x);                     \
        B64[(r+1)*(BSD_STRIDE/2)+posU] = pack2(w0.y, w0.y);                     \
        B64[(r+2)*(BSD_STRIDE/2)+posU] = pack2(w0.z, w0.z);                     \
        B64[(r+3)*(BSD_STRIDE/2)+posU] = pack2(w0.w, w0.w);                     \
        B64[(r+4)*(BSD_STRIDE/2)+posU] = pack2(w1.x, w1.x);                     \
        B64[(r+5)*(BSD_STRIDE/2)+posU] = pack2(w1.y, w1.y);                     \
        B64[(r+6)*(BSD_STRIDE/2)+posU] = pack2(w1.z, w1.z);                     \
        B64[(r+7)*(BSD_STRIDE/2)+posU] = pack2(w1.w, w1.w);                     \
    }

// ---------------- pre: [NT*NB, 256] x [256, 512] GEMM ----------------
__global__ __launch_bounds__(256)
void pre_kernel(const float* __restrict__ x, const float* __restrict__ W_ih) {
    __shared__ float As[32 * 64];
    __shared__ float Bsd[32 * BSD_STRIDE];
    int r0 = blockIdx.x * 64;   // rows r = t*1024 + b  (same t across the tile)
    int g0 = blockIdx.y * 64;   // gate cols
    int tid = threadIdx.x;
    int tx = tid & 15, ty = tid >> 4;
    int lane = tid & 63, kg = tid >> 6;

    int r = r0 + lane;
    int b = r & 1023, t = r >> 10;
    const float* xrow = x + (size_t)(b * NT + t) * ND + kg * 8;
    const float* wrow = W_ih + (size_t)(g0 + lane) * 768 + kg * 8;

    ull acc[2][4];
    #pragma unroll
    for (int i = 0; i < 2; i++)
        #pragma unroll
        for (int j = 0; j < 4; j++) acc[i][j] = 0ull;

    float4 a0 = *(const float4*)(xrow);
    float4 a1 = *(const float4*)(xrow + 4);
    float4 w0 = *(const float4*)(wrow);
    float4 w1 = *(const float4*)(wrow + 4);

    for (int kt = 0; kt < ND / 32; kt++) {
        STORE_TILES(As, Bsd, lane, kg, a0, a1, w0, w1);
        __syncthreads();
        if (kt + 1 < ND / 32) {
            int k0 = (kt + 1) * 32;
            a0 = *(const float4*)(xrow + k0);
            a1 = *(const float4*)(xrow + k0 + 4);
            w0 = *(const float4*)(wrow + k0);
            w1 = *(const float4*)(wrow + k0 + 4);
        }
        GEMM_COMPUTE(As, Bsd, acc, tx, ty);
        __syncthreads();
    }

    int tt = r0 >> 10;
    #pragma unroll
    for (int ih = 0; ih < 2; ih++) {
        float2 c0 = unpack2(acc[ih][0]);
        float2 c1 = unpack2(acc[ih][1]);
        float2 c2 = unpack2(acc[ih][2]);
        float2 c3 = unpack2(acc[ih][3]);
        int g = g0 + tx * 4;
        float b0v = g_bias[g], b1v = g_bias[g + 1], b2v = g_bias[g + 2], b3v = g_bias[g + 3];
        if (tt == 0) {
            b0v += g_const0[g]; b1v += g_const0[g + 1];
            b2v += g_const0[g + 2]; b3v += g_const0[g + 3];
        }
        int rr = r0 + ty * 4 + 2 * ih;
        float4 v0 = make_float4(c0.x + b0v, c1.x + b1v, c2.x + b2v, c3.x + b3v);
        float4 v1 = make_float4(c0.y + b0v, c1.y + b1v, c2.y + b2v, c3.y + b3v);
        *(float4*)(g_pre + (size_t)rr * NG + g) = v0;
        *(float4*)(g_pre + (size_t)(rr + 1) * NG + g) = v1;
    }
}

// ---------------- init ----------------
__global__ void init_kernel() {
    int i = blockIdx.x * blockDim.x + threadIdx.x;
    if (i < NB * NH) { g_hA[i] = 0.f; g_c[i] = 0.f; g_hsum[i] = 0.f; }
}

// ---------------- one recurrent step ----------------
__global__ __launch_bounds__(256)
void step_kernel(int t) {
    const float* __restrict__ Hp = (t & 1) ? g_hB : g_hA;
    float* __restrict__ Hn = (t & 1) ? g_hA : g_hB;

    __shared__ float As[32 * 64];
    __shared__ float Bsd[32 * BSD_STRIDE];
    int b0  = blockIdx.x * 64;   // batch tile
    int rr0 = blockIdx.y * 64;   // reordered gate rows (16 units x 4 gates)
    int tid = threadIdx.x;
    int tx = tid & 15, ty = tid >> 4;
    int lane = tid & 63, kg = tid >> 6;

    const float* wrow = g_Wro + (size_t)(rr0 + lane) * NK + kg * 8;
    int bb = b0 + lane;

    ull acc[2][4];
    #pragma unroll
    for (int i = 0; i < 2; i++)
        #pragma unroll
        for (int j = 0; j < 4; j++) acc[i][j] = 0ull;

    // prefetch slab 0 (k0 = 0 -> W_hh segment: src = b)
    const float* hp0 = Hp + bb * NH + kg * 8;
    float4 a0 = *(const float4*)(hp0);
    float4 a1 = *(const float4*)(hp0 + 4);
    float4 w0 = *(const float4*)(wrow);
    float4 w1 = *(const float4*)(wrow + 4);

    for (int kt = 0; kt < NK / 32; kt++) {
        STORE_TILES(As, Bsd, lane, kg, a0, a1, w0, w1);
        __syncthreads();
        if (kt + 1 < NK / 32) {
            int k0 = (kt + 1) * 32;
            int src, cb;
            if (k0 < 128) { src = bb; cb = k0; }
            else { int q = (k0 - 128) >> 7; src = (4 * bb + q) & 1023; cb = (k0 - 128) & 127; }
            const float* hp = Hp + src * NH + cb + kg * 8;
            a0 = *(const float4*)(hp);
            a1 = *(const float4*)(hp + 4);
            w0 = *(const float4*)(wrow + k0);
            w1 = *(const float4*)(wrow + k0 + 4);
        }
        GEMM_COMPUTE(As, Bsd, acc, tx, ty);
        __syncthreads();
    }

    // LSTM pointwise: col tx*4+j -> unit u = rr0/4 + tx, gate j
    int u = (rr0 >> 2) + tx;
    #pragma unroll
    for (int ih = 0; ih < 2; ih++) {
        float2 ai = unpack2(acc[ih][0]);
        float2 af = unpack2(acc[ih][1]);
        float2 ag = unpack2(acc[ih][2]);
        float2 ao = unpack2(acc[ih][3]);
        #pragma unroll
        for (int s = 0; s < 2; s++) {
            int b = b0 + ty * 4 + 2 * ih + s;
            size_t pb = ((size_t)t * NB + b) * NG;
            float gi = (s ? ai.y : ai.x) + g_pre[pb + u];
            float gf = (s ? af.y : af.x) + g_pre[pb + 128 + u];
            float gg = (s ? ag.y : ag.x) + g_pre[pb + 256 + u];
            float go = (s ? ao.y : ao.x) + g_pre[pb + 384 + u];
            float si = 1.f / (1.f + expf(-gi));
            float sf = 1.f / (1.f + expf(-gf));
            float so = 1.f / (1.f + expf(-go));
            float tg = tanhf(gg);
            int idx = b * NH + u;
            float c = sf * g_c[idx] + si * tg;
            g_c[idx] = c;
            float h = so * tanhf(c);
            Hn[idx] = h;
            g_hsum[idx] += h;
        }
    }
}

// ---------------- final ----------------
__global__ void final_kernel(float* __restrict__ out, const float* __restrict__ fc_b) {
    int b = blockIdx.x * blockDim.x + threadIdx.x;
    if (b >= NB) return;
    #pragma unroll
    for (int o = 0; o < 2; o++) {
        const float* f = g_fA + o * NK;
        const float* hs = g_hsum + b * NH;
        float s = 0.f;
        for (int k = 0; k < NH; k++) s += f[k] * hs[k];
        #pragma unroll
        for (int q = 0; q < 4; q++) {
            const float* hq = g_hsum + ((4 * b + q) & 1023) * NH;
            const float* fq = f + 128 + q * 128;
            for (int m = 0; m < NH; m++) s += fq[m] * hq[m];
        }
        out[b * 2 + o] = fc_b[o] + s * (1.f / (float)NT);
    }
}

// ---------------- launch ----------------
extern "C" void kernel_launch(void* const* d_in, const int* in_sizes, int n_in,
                              void* d_out, int out_size) {
    const float* x      = (const float*)d_in[0];
    const float* memory = (const float*)d_in[1];
    const float* rv0    = (const float*)d_in[2];
    const float* W_ih   = (const float*)d_in[3];
    const float* W_hh   = (const float*)d_in[4];
    const float* b_ih   = (const float*)d_in[5];
    const float* b_hh   = (const float*)d_in[6];
    const float* fc_w   = (const float*)d_in[7];
    const float* fc_b   = (const float*)d_in[8];
    float* out = (float*)d_out;

    setup_kernel<<<1, 128>>>(memory, b_ih, b_hh, rv0, W_ih);
    buildA_kernel<<<dim3(514, 5), 128>>>(W_ih, W_hh, fc_w);
    pre_kernel<<<dim3((NT * NB) / 64, NG / 64), 256>>>(x, W_ih);
    init_kernel<<<dim3((NB * NH + 255) / 256), 256>>>();
    for (int t = 0; t < NT; t++)
        step_kernel<<<dim3(NB / 64, NG / 64), 256>>>(t);
    final_kernel<<<dim3(4), 256>>>(out, fc_b);
}

// round 4
// speedup vs baseline: 1.2283x; 1.0380x over previous
#include <cuda_runtime.h>

// ---------------- problem constants ----------------
#define NB 1024   // batch
#define NT 128    // timesteps
#define ND 256    // d_in
#define NH 128    // hidden == memory units == memory width
#define NG 512    // 4*NH gates
#define NK 640    // 128 (hh) + 512 (rv via A_q)

typedef unsigned long long ull;

// ---------------- f32x2 packed math ----------------
__device__ __forceinline__ ull ffma2(ull a, ull b, ull c) {
    ull d;
    asm("fma.rn.f32x2 %0, %1, %2, %3;" : "=l"(d) : "l"(a), "l"(b), "l"(c));
    return d;
}
__device__ __forceinline__ float2 unpack2(ull v) {
    float2 r; asm("mov.b64 {%0, %1}, %2;" : "=f"(r.x), "=f"(r.y) : "l"(v)); return r;
}

__device__ __forceinline__ float sig_fast(float x) {
    return 1.0f / (1.0f + __expf(-x));
}
__device__ __forceinline__ float tanh_fast(float x) {
    return 2.0f / (1.0f + __expf(-2.0f * x)) - 1.0f;
}

// ---------------- device scratch ----------------
__device__ float g_pre[(size_t)NT * NB * NG];   // [t*NB+b][g]
__device__ float g_Wro[NG * NK];                // row rr=4u+gate, cols [W_hh | A_0..A_3]
__device__ float g_memsm[NH * NH];
__device__ float g_fA[2 * NK];
__device__ float g_hA[NB * NH];
__device__ float g_hB[NB * NH];
__device__ float g_c[NB * NH];
__device__ float g_hsum[NB * NH];
__device__ float g_bias[NG];
__device__ float g_const0[NG];

// ---------------- GEMM tile core (64x64, K-slab 32, k-pair packed, XOR swizzle) ----
// smem tile: per row c (0..63), 8 float4 "quads" q at phys = c*8 + (q ^ K(c)),
// K(c) = ((c>>2) ^ (2*(c&3))) & 7.  Loads (cols strided by 4) AND stores
// (rows linear) are both conflict-free.

__device__ __forceinline__ void store_tile(float4* As4, float4* Bs4, int lane, int kg,
                                           float4 a0, float4 a1, float4 w0, float4 w1) {
    int K = ((lane >> 2) ^ (2 * (lane & 3))) & 7;
    int q0 = 2 * kg;
    As4[lane * 8 + (q0 ^ K)]       = a0;
    As4[lane * 8 + ((q0 + 1) ^ K)] = a1;
    Bs4[lane * 8 + (q0 ^ K)]       = w0;
    Bs4[lane * 8 + ((q0 + 1) ^ K)] = w1;
}

__device__ __forceinline__ void gemm_slab(const float4* As4, const float4* Bs4,
                                          ull acc[4][4], int tx, int ty) {
    int Ka = ty & 7;   // row c = ty*4+i  -> K(c) = (ty&7) ^ (2i)
    int Kb = tx & 7;   // col c = tx*4+j  -> K(c) = (tx&7) ^ (2j)
    #pragma unroll
    for (int q = 0; q < 8; q++) {
        ulonglong2 a[4], b[4];
        #pragma unroll
        for (int i = 0; i < 4; i++)
            a[i] = *(const ulonglong2*)(As4 + (ty * 4 + i) * 8 + ((q ^ (2 * i)) ^ Ka));
        #pragma unroll
        for (int j = 0; j < 4; j++)
            b[j] = *(const ulonglong2*)(Bs4 + (tx * 4 + j) * 8 + ((q ^ (2 * j)) ^ Kb));
        #pragma unroll
        for (int i = 0; i < 4; i++)
            #pragma unroll
            for (int j = 0; j < 4; j++) {
                acc[i][j] = ffma2(a[i].x, b[j].x, acc[i][j]);
                acc[i][j] = ffma2(a[i].y, b[j].y, acc[i][j]);
            }
    }
}

// ---------------- init ----------------
__global__ void init_kernel() {
    int i = blockIdx.x * blockDim.x + threadIdx.x;
    if (i < NB * NH) { g_hA[i] = 0.f; g_c[i] = 0.f; g_hsum[i] = 0.f; }
}

// ---------------- setup: softmax, bias, rv0 constant ----------------
__global__ void setup_kernel(const float* __restrict__ memory,
                             const float* __restrict__ b_ih,
                             const float* __restrict__ b_hh,
                             const float* __restrict__ rv0,
                             const float* __restrict__ W_ih) {
    int tid = threadIdx.x;
    float mx = -1e30f;
    for (int m = 0; m < NH; m++) mx = fmaxf(mx, memory[m * NH + tid]);
    float s = 0.f;
    for (int m = 0; m < NH; m++) s += expf(memory[m * NH + tid] - mx);
    float inv = 1.f / s;
    for (int m = 0; m < NH; m++)
        g_memsm[m * NH + tid] = expf(memory[m * NH + tid] - mx) * inv;

    for (int g = tid; g < NG; g += 128) {
        g_bias[g] = b_ih[g] + b_hh[g];
        float c0 = 0.f;
        const float* w = W_ih + (size_t)g * 768 + 256;
        for (int k = 0; k < 512; k++) c0 += rv0[k] * w[k];
        g_const0[g] = c0;
    }
}

// ---------------- fold mem_sm into W_ih (A_q) and fc_w ----------------
__global__ void buildA_kernel(const float* __restrict__ W_ih,
                              const float* __restrict__ W_hh,
                              const float* __restrict__ fc_w) {
    int row = blockIdx.x;   // 0..513
    int q   = blockIdx.y;   // 0..4
    int j   = threadIdx.x;  // 0..127
    if (row < NG) {
        int u = row >> 2, gate = row & 3;
        int go = gate * 128 + u;
        if (q == 0) {
            g_Wro[(size_t)row * NK + j] = W_hh[(size_t)go * NH + j];
        } else {
            const float* w = W_ih + (size_t)go * 768 + 256 + (q - 1) * 128;
            float s = 0.f;
            for (int m = 0; m < NH; m++) s += w[m] * g_memsm[m * NH + j];
            g_Wro[(size_t)row * NK + q * 128 + j] = s;
        }
    } else {
        int o = row - NG;
        if (q == 0) {
            g_fA[o * NK + j] = fc_w[o * NK + j];
        } else {
            const float* w = fc_w + o * NK + 128 + (q - 1) * 128;
            float s = 0.f;
            for (int m = 0; m < NH; m++) s += w[m] * g_memsm[m * NH + j];
            g_fA[o * NK + q * 128 + j] = s;
        }
    }
}

// ---------------- pre: [NT*NB, 256] x [256, 512] GEMM ----------------
__global__ __launch_bounds__(256)
void pre_kernel(const float* __restrict__ x, const float* __restrict__ W_ih) {
    __shared__ float4 sm[4 * 512];   // As0, Bs0, As1, Bs1 (8 KB each)
    float4* buf[2][2] = {{sm, sm + 512}, {sm + 1024, sm + 1536}};

    int r0 = blockIdx.x * 64;   // rows r = t*1024 + b  (same t across tile)
    int g0 = blockIdx.y * 64;
    int tid = threadIdx.x;
    int tx = tid & 15, ty = tid >> 4;
    int lane = tid & 63, kg = tid >> 6;

    int r = r0 + lane;
    int b = r & 1023, t = r >> 10;
    const float* xrow = x + (size_t)(b * NT + t) * ND + kg * 8;
    const float* wrow = W_ih + (size_t)(g0 + lane) * 768 + kg * 8;

    ull acc[4][4];
    #pragma unroll
    for (int i = 0; i < 4; i++)
        #pragma unroll
        for (int j = 0; j < 4; j++) acc[i][j] = 0ull;

    const int NS = ND / 32;   // 8 slabs
    float4 a0 = *(const float4*)(xrow);
    float4 a1 = *(const float4*)(xrow + 4);
    float4 w0 = *(const float4*)(wrow);
    float4 w1 = *(const float4*)(wrow + 4);
    store_tile(buf[0][0], buf[0][1], lane, kg, a0, a1, w0, w1);
    a0 = *(const float4*)(xrow + 32);
    a1 = *(const float4*)(xrow + 36);
    w0 = *(const float4*)(wrow + 32);
    w1 = *(const float4*)(wrow + 36);
    __syncthreads();

    for (int kt = 0; kt < NS; kt++) {
        int cur = kt & 1;
        if (kt + 1 < NS) store_tile(buf[cur ^ 1][0], buf[cur ^ 1][1], lane, kg, a0, a1, w0, w1);
        if (kt + 2 < NS) {
            int k0 = (kt + 2) * 32;
            a0 = *(const float4*)(xrow + k0);
            a1 = *(const float4*)(xrow + k0 + 4);
            w0 = *(const float4*)(wrow + k0);
            w1 = *(const float4*)(wrow + k0 + 4);
        }
        gemm_slab(buf[cur][0], buf[cur][1], acc, tx, ty);
        __syncthreads();
    }

    int tt = r0 >> 10;
    #pragma unroll
    for (int i = 0; i < 4; i++) {
        int rr = r0 + ty * 4 + i;
        int g = g0 + tx * 4;
        float4 v;
        float2 c0 = unpack2(acc[i][0]);
        float2 c1 = unpack2(acc[i][1]);
        float2 c2 = unpack2(acc[i][2]);
        float2 c3 = unpack2(acc[i][3]);
        v.x = c0.x + c0.y + g_bias[g];
        v.y = c1.x + c1.y + g_bias[g + 1];
        v.z = c2.x + c2.y + g_bias[g + 2];
        v.w = c3.x + c3.y + g_bias[g + 3];
        if (tt == 0) {
            v.x += g_const0[g]; v.y += g_const0[g + 1];
            v.z += g_const0[g + 2]; v.w += g_const0[g + 3];
        }
        *(float4*)(g_pre + (size_t)rr * NG + g) = v;
    }
}

// ---------------- one recurrent step ----------------
__global__ __launch_bounds__(256)
void step_kernel(int t) {
    const float* __restrict__ Hp = (t & 1) ? g_hB : g_hA;
    float* __restrict__ Hn = (t & 1) ? g_hA : g_hB;

    __shared__ float4 sm[4 * 512];
    float4* buf[2][2] = {{sm, sm + 512}, {sm + 1024, sm + 1536}};

    int b0  = blockIdx.x * 64;
    int rr0 = blockIdx.y * 64;
    int tid = threadIdx.x;
    int tx = tid & 15, ty = tid >> 4;
    int lane = tid & 63, kg = tid >> 6;

    const float* wrow = g_Wro + (size_t)(rr0 + lane) * NK + kg * 8;
    int bb = b0 + lane;

    ull acc[4][4];
    #pragma unroll
    for (int i = 0; i < 4; i++)
        #pragma unroll
        for (int j = 0; j < 4; j++) acc[i][j] = 0ull;

    const int NS = NK / 32;   // 20 slabs

    // gather address for slab s
    auto aptr = [&](int s) -> const float* {
        int k0 = s * 32;
        int src, cb;
        if (k0 < 128) { src = bb; cb = k0; }
        else { int q = (k0 - 128) >> 7; src = (4 * bb + q) & 1023; cb = (k0 - 128) & 127; }
        return Hp + src * NH + cb + kg * 8;
    };

    const float* ap = aptr(0);
    float4 a0 = *(const float4*)(ap);
    float4 a1 = *(const float4*)(ap + 4);
    float4 w0 = *(const float4*)(wrow);
    float4 w1 = *(const float4*)(wrow + 4);
    store_tile(buf[0][0], buf[0][1], lane, kg, a0, a1, w0, w1);
    ap = aptr(1);
    a0 = *(const float4*)(ap);
    a1 = *(const float4*)(ap + 4);
    w0 = *(const float4*)(wrow + 32);
    w1 = *(const float4*)(wrow + 36);
    __syncthreads();

    for (int kt = 0; kt < NS; kt++) {
        int cur = kt & 1;
        if (kt + 1 < NS) store_tile(buf[cur ^ 1][0], buf[cur ^ 1][1], lane, kg, a0, a1, w0, w1);
        if (kt + 2 < NS) {
            int k0 = (kt + 2) * 32;
            ap = aptr(kt + 2);
            a0 = *(const float4*)(ap);
            a1 = *(const float4*)(ap + 4);
            w0 = *(const float4*)(wrow + k0);
            w1 = *(const float4*)(wrow + k0 + 4);
        }
        gemm_slab(buf[cur][0], buf[cur][1], acc, tx, ty);
        __syncthreads();
    }

    // LSTM pointwise: batch b = b0+ty*4+i, unit u = rr0/4 + tx, gate = j
    int u = (rr0 >> 2) + tx;
    #pragma unroll
    for (int i = 0; i < 4; i++) {
        int b = b0 + ty * 4 + i;
        size_t pb = ((size_t)t * NB + b) * NG;
        float2 ai = unpack2(acc[i][0]);
        float2 af = unpack2(acc[i][1]);
        float2 ag = unpack2(acc[i][2]);
        float2 ao = unpack2(acc[i][3]);
        float gi = ai.x + ai.y + g_pre[pb + u];
        float gf = af.x + af.y + g_pre[pb + 128 + u];
        float gg = ag.x + ag.y + g_pre[pb + 256 + u];
        float go = ao.x + ao.y + g_pre[pb + 384 + u];
        float si = sig_fast(gi);
        float sf = sig_fast(gf);
        float so = sig_fast(go);
        float tg = tanh_fast(gg);
        int idx = b * NH + u;
        float c = sf * g_c[idx] + si * tg;
        g_c[idx] = c;
        float h = so * tanh_fast(c);
        Hn[idx] = h;
        g_hsum[idx] += h;
    }
}

// ---------------- final ----------------
__global__ void final_kernel(float* __restrict__ out, const float* __restrict__ fc_b) {
    int b = blockIdx.x * blockDim.x + threadIdx.x;
    if (b >= NB) return;
    #pragma unroll
    for (int o = 0; o < 2; o++) {
        const float* f = g_fA + o * NK;
        const float* hs = g_hsum + b * NH;
        float s = 0.f;
        for (int k = 0; k < NH; k++) s += f[k] * hs[k];
        #pragma unroll
        for (int q = 0; q < 4; q++) {
            const float* hq = g_hsum + ((4 * b + q) & 1023) * NH;
            const float* fq = f + 128 + q * 128;
            for (int m = 0; m < NH; m++) s += fq[m] * hq[m];
        }
        out[b * 2 + o] = fc_b[o] + s * (1.f / (float)NT);
    }
}

// ---------------- launch ----------------
extern "C" void kernel_launch(void* const* d_in, const int* in_sizes, int n_in,
                              void* d_out, int out_size) {
    const float* x      = (const float*)d_in[0];
    const float* memory = (const float*)d_in[1];
    const float* rv0    = (const float*)d_in[2];
    const float* W_ih   = (const float*)d_in[3];
    const float* W_hh   = (const float*)d_in[4];
    const float* b_ih   = (const float*)d_in[5];
    const float* b_hh   = (const float*)d_in[6];
    const float* fc_w   = (const float*)d_in[7];
    const float* fc_b   = (const float*)d_in[8];
    float* out = (float*)d_out;

    init_kernel<<<dim3((NB * NH + 255) / 256), 256>>>();
    setup_kernel<<<1, 128>>>(memory, b_ih, b_hh, rv0, W_ih);
    buildA_kernel<<<dim3(514, 5), 128>>>(W_ih, W_hh, fc_w);
    pre_kernel<<<dim3((NT * NB) / 64, NG / 64), 256>>>(x, W_ih);
    for (int t = 0; t < NT; t++)
        step_kernel<<<dim3(NB / 64, NG / 64), 256>>>(t);
    final_kernel<<<dim3(4), 256>>>(out, fc_b);
}

// round 5
// speedup vs baseline: 1.8463x; 1.5032x over previous
#include <cuda_runtime.h>

// ---------------- problem constants ----------------
#define NB 1024   // batch
#define NT 128    // timesteps
#define ND 256    // d_in
#define NH 128    // hidden
#define NG 512    // 4*NH gates
#define NK 640    // 128 (hh) + 512 (rv via A_q)
#define NSPLIT 2  // K-split for step GEMM

typedef unsigned long long ull;

// ---------------- f32x2 packed math ----------------
__device__ __forceinline__ ull ffma2(ull a, ull b, ull c) {
    ull d;
    asm("fma.rn.f32x2 %0, %1, %2, %3;" : "=l"(d) : "l"(a), "l"(b), "l"(c));
    return d;
}
__device__ __forceinline__ float2 unpack2(ull v) {
    float2 r; asm("mov.b64 {%0, %1}, %2;" : "=f"(r.x), "=f"(r.y) : "l"(v)); return r;
}
__device__ __forceinline__ float sig_fast(float x) { return 1.0f / (1.0f + __expf(-x)); }
__device__ __forceinline__ float tanh_fast(float x) { return 2.0f / (1.0f + __expf(-2.0f * x)) - 1.0f; }

__device__ __forceinline__ unsigned smem_u32(const void* p) {
    unsigned r;
    asm("{ .reg .u64 t; cvta.to.shared.u64 t, %1; cvt.u32.u64 %0, t; }" : "=r"(r) : "l"(p));
    return r;
}
#define CP16(dst, src) asm volatile("cp.async.cg.shared.global [%0], [%1], 16;" :: "r"(dst), "l"(src))
#define CP_COMMIT()    asm volatile("cp.async.commit_group;")
#define CP_WAIT1()     asm volatile("cp.async.wait_group 1;")
#define CP_WAIT0()     asm volatile("cp.async.wait_group 0;")

// ---------------- device scratch ----------------
__device__ float g_pre[(size_t)NT * NB * NG];   // [t*NB+b][g]
__device__ float g_Wro[NG * NK];                // row rr=4u+gate, cols [W_hh | A_0..A_3]
__device__ float g_part[NSPLIT][NB * NG];       // split-K partials [b*NG + rr]
__device__ float g_memsm[NH * NH];
__device__ float g_fA[2 * NK];
__device__ float g_hA[NB * NH];
__device__ float g_hB[NB * NH];
__device__ float g_c[NB * NH];
__device__ float g_hsum[NB * NH];
__device__ float g_bias[NG];
__device__ float g_const0[NG];

// ---------------- GEMM tile compute (64x64, K-slab 32, k-pair packed, XOR swizzle) ----
// per row c (0..63), 8 float4 quads q at phys = c*8 + (q ^ K(c)), K(c)=((c>>2)^(2*(c&3)))&7
__device__ __forceinline__ void gemm_slab(const float4* As4, const float4* Bs4,
                                          ull acc[4][4], int tx, int ty) {
    int Ka = ty & 7;
    int Kb = tx & 7;
    #pragma unroll
    for (int q = 0; q < 8; q++) {
        ulonglong2 a[4], b[4];
        #pragma unroll
        for (int i = 0; i < 4; i++)
            a[i] = *(const ulonglong2*)(As4 + (ty * 4 + i) * 8 + ((q ^ (2 * i)) ^ Ka));
        #pragma unroll
        for (int j = 0; j < 4; j++)
            b[j] = *(const ulonglong2*)(Bs4 + (tx * 4 + j) * 8 + ((q ^ (2 * j)) ^ Kb));
        #pragma unroll
        for (int i = 0; i < 4; i++)
            #pragma unroll
            for (int j = 0; j < 4; j++) {
                acc[i][j] = ffma2(a[i].x, b[j].x, acc[i][j]);
                acc[i][j] = ffma2(a[i].y, b[j].y, acc[i][j]);
            }
    }
}

// ---------------- init ----------------
__global__ void init_kernel() {
    int i = blockIdx.x * blockDim.x + threadIdx.x;
    if (i < NB * NH) { g_hA[i] = 0.f; g_c[i] = 0.f; g_hsum[i] = 0.f; }
}

// ---------------- setup ----------------
__global__ void setup_kernel(const float* __restrict__ memory,
                             const float* __restrict__ b_ih,
                             const float* __restrict__ b_hh,
                             const float* __restrict__ rv0,
                             const float* __restrict__ W_ih) {
    int tid = threadIdx.x;
    float mx = -1e30f;
    for (int m = 0; m < NH; m++) mx = fmaxf(mx, memory[m * NH + tid]);
    float s = 0.f;
    for (int m = 0; m < NH; m++) s += expf(memory[m * NH + tid] - mx);
    float inv = 1.f / s;
    for (int m = 0; m < NH; m++)
        g_memsm[m * NH + tid] = expf(memory[m * NH + tid] - mx) * inv;

    for (int g = tid; g < NG; g += 128) {
        g_bias[g] = b_ih[g] + b_hh[g];
        float c0 = 0.f;
        const float* w = W_ih + (size_t)g * 768 + 256;
        for (int k = 0; k < 512; k++) c0 += rv0[k] * w[k];
        g_const0[g] = c0;
    }
}

// ---------------- fold mem_sm into weights ----------------
__global__ void buildA_kernel(const float* __restrict__ W_ih,
                              const float* __restrict__ W_hh,
                              const float* __restrict__ fc_w) {
    int row = blockIdx.x, q = blockIdx.y, j = threadIdx.x;
    if (row < NG) {
        int u = row >> 2, gate = row & 3;
        int go = gate * 128 + u;
        if (q == 0) {
            g_Wro[(size_t)row * NK + j] = W_hh[(size_t)go * NH + j];
        } else {
            const float* w = W_ih + (size_t)go * 768 + 256 + (q - 1) * 128;
            float s = 0.f;
            for (int m = 0; m < NH; m++) s += w[m] * g_memsm[m * NH + j];
            g_Wro[(size_t)row * NK + q * 128 + j] = s;
        }
    } else {
        int o = row - NG;
        if (q == 0) {
            g_fA[o * NK + j] = fc_w[o * NK + j];
        } else {
            const float* w = fc_w + o * NK + 128 + (q - 1) * 128;
            float s = 0.f;
            for (int m = 0; m < NH; m++) s += w[m] * g_memsm[m * NH + j];
            g_fA[o * NK + q * 128 + j] = s;
        }
    }
}

// ---------------- pre: [NT*NB, 256] x [256, 512] GEMM ----------------
__global__ __launch_bounds__(256, 2)
void pre_kernel(const float* __restrict__ x, const float* __restrict__ W_ih) {
    __shared__ float4 sm[3 * 1024];   // 3 stages x (As 512 + Bs 512) = 48 KB

    int r0 = blockIdx.x * 64;   // rows r = t*1024 + b  (same t per tile)
    int g0 = blockIdx.y * 64;
    int tid = threadIdx.x;
    int tx = tid & 15, ty = tid >> 4;
    int lane = tid & 63, kg = tid >> 6;
    int K = ((lane >> 2) ^ (2 * (lane & 3))) & 7;
    int q0 = 2 * kg;

    int r = r0 + lane;
    int b = r & 1023, t = r >> 10;
    const float* xrow = x + (size_t)(b * NT + t) * ND + kg * 8;
    const float* wrow = W_ih + (size_t)(g0 + lane) * 768 + kg * 8;

    unsigned smbase = smem_u32(sm) + ((unsigned)(lane * 8) << 4);
    unsigned o0 = (unsigned)(q0 ^ K) << 4;
    unsigned o1 = (unsigned)((q0 + 1) ^ K) << 4;

    ull acc[4][4];
    #pragma unroll
    for (int i = 0; i < 4; i++)
        #pragma unroll
        for (int j = 0; j < 4; j++) acc[i][j] = 0ull;

    const int NS = ND / 32;   // 8

    #define PRE_ISSUE(s)                                                   \
    {                                                                      \
        unsigned ab = smbase + (((s) % 3) * 1024u << 4);                   \
        unsigned bb2 = ab + (512u << 4);                                   \
        const float* ap = xrow + (s) * 32;                                 \
        const float* wp = wrow + (s) * 32;                                 \
        CP16(ab + o0, ap); CP16(ab + o1, ap + 4);                          \
        CP16(bb2 + o0, wp); CP16(bb2 + o1, wp + 4);                        \
        CP_COMMIT();                                                       \
    }

    PRE_ISSUE(0);
    PRE_ISSUE(1);
    for (int kt = 0; kt < NS; kt++) {
        if (kt + 2 < NS) CP_WAIT1(); else CP_WAIT0();
        __syncthreads();
        if (kt + 2 < NS) PRE_ISSUE(kt + 2);
        const float4* As4 = sm + (kt % 3) * 1024;
        gemm_slab(As4, As4 + 512, acc, tx, ty);
    }
    #undef PRE_ISSUE

    int tt = r0 >> 10;
    #pragma unroll
    for (int i = 0; i < 4; i++) {
        int rr = r0 + ty * 4 + i;
        int g = g0 + tx * 4;
        float2 c0 = unpack2(acc[i][0]);
        float2 c1 = unpack2(acc[i][1]);
        float2 c2 = unpack2(acc[i][2]);
        float2 c3 = unpack2(acc[i][3]);
        float4 v;
        v.x = c0.x + c0.y + g_bias[g];
        v.y = c1.x + c1.y + g_bias[g + 1];
        v.z = c2.x + c2.y + g_bias[g + 2];
        v.w = c3.x + c3.y + g_bias[g + 3];
        if (tt == 0) {
            v.x += g_const0[g]; v.y += g_const0[g + 1];
            v.z += g_const0[g + 2]; v.w += g_const0[g + 3];
        }
        *(float4*)(g_pre + (size_t)rr * NG + g) = v;
    }
}

// ---------------- step GEMM (split-K): partial gates ----------------
__global__ __launch_bounds__(256, 2)
void stepmm_kernel(int t) {
    const float* __restrict__ Hp = (t & 1) ? g_hB : g_hA;

    __shared__ float4 sm[3 * 1024];

    int b0  = blockIdx.x * 64;   // batch tile (rows)
    int rr0 = blockIdx.y * 64;   // gate-row tile (cols)
    int sp  = blockIdx.z;        // K split
    int tid = threadIdx.x;
    int tx = tid & 15, ty = tid >> 4;
    int lane = tid & 63, kg = tid >> 6;
    int K = ((lane >> 2) ^ (2 * (lane & 3))) & 7;
    int q0 = 2 * kg;

    const float* wrow = g_Wro + (size_t)(rr0 + lane) * NK + kg * 8;
    int bb = b0 + lane;

    unsigned smbase = smem_u32(sm) + ((unsigned)(lane * 8) << 4);
    unsigned o0 = (unsigned)(q0 ^ K) << 4;
    unsigned o1 = (unsigned)((q0 + 1) ^ K) << 4;

    ull acc[4][4];
    #pragma unroll
    for (int i = 0; i < 4; i++)
        #pragma unroll
        for (int j = 0; j < 4; j++) acc[i][j] = 0ull;

    const int NS = NK / 32 / NSPLIT;   // 10
    int base = sp * NS;

    #define STEP_ISSUE(s)                                                  \
    {                                                                      \
        int sg = base + (s);                                               \
        int k0 = sg * 32;                                                  \
        int src, cb;                                                       \
        if (k0 < 128) { src = bb; cb = k0; }                               \
        else { int q = (k0 - 128) >> 7; src = (4 * bb + q) & 1023; cb = (k0 - 128) & 127; } \
        const float* ap = Hp + src * NH + cb + kg * 8;                     \
        const float* wp = wrow + k0;                                       \
        unsigned ab = smbase + (((s) % 3) * 1024u << 4);                   \
        unsigned bb2 = ab + (512u << 4);                                   \
        CP16(ab + o0, ap); CP16(ab + o1, ap + 4);                          \
        CP16(bb2 + o0, wp); CP16(bb2 + o1, wp + 4);                        \
        CP_COMMIT();                                                       \
    }

    STEP_ISSUE(0);
    STEP_ISSUE(1);
    for (int kt = 0; kt < NS; kt++) {
        if (kt + 2 < NS) CP_WAIT1(); else CP_WAIT0();
        __syncthreads();
        if (kt + 2 < NS) STEP_ISSUE(kt + 2);
        const float4* As4 = sm + (kt % 3) * 1024;
        gemm_slab(As4, As4 + 512, acc, tx, ty);
    }
    #undef STEP_ISSUE

    float* part = g_part[sp];
    #pragma unroll
    for (int i = 0; i < 4; i++) {
        int b = b0 + ty * 4 + i;
        int rr = rr0 + tx * 4;
        float2 c0 = unpack2(acc[i][0]);
        float2 c1 = unpack2(acc[i][1]);
        float2 c2 = unpack2(acc[i][2]);
        float2 c3 = unpack2(acc[i][3]);
        float4 v = make_float4(c0.x + c0.y, c1.x + c1.y, c2.x + c2.y, c3.x + c3.y);
        *(float4*)(part + (size_t)b * NG + rr) = v;
    }
}

// ---------------- pointwise: reduce splits + LSTM ----------------
__global__ __launch_bounds__(256)
void lstm_kernel(int t) {
    float* __restrict__ Hn = (t & 1) ? g_hA : g_hB;
    int idx = blockIdx.x * 256 + threadIdx.x;   // 0 .. NB*NH-1
    int b = idx >> 7;
    int u = idx & 127;

    float4 p0 = *(const float4*)(g_part[0] + (size_t)b * NG + 4 * u);
    float4 p1 = *(const float4*)(g_part[1] + (size_t)b * NG + 4 * u);
    size_t pb = ((size_t)t * NB + b) * NG;
    float gi = p0.x + p1.x + g_pre[pb + u];
    float gf = p0.y + p1.y + g_pre[pb + 128 + u];
    float gg = p0.z + p1.z + g_pre[pb + 256 + u];
    float go = p0.w + p1.w + g_pre[pb + 384 + u];

    float si = sig_fast(gi);
    float sf = sig_fast(gf);
    float so = sig_fast(go);
    float tg = tanh_fast(gg);
    float c = sf * g_c[idx] + si * tg;
    g_c[idx] = c;
    float h = so * tanh_fast(c);
    Hn[idx] = h;
    g_hsum[idx] += h;
}

// ---------------- final ----------------
__global__ void final_kernel(float* __restrict__ out, const float* __restrict__ fc_b) {
    int b = blockIdx.x * blockDim.x + threadIdx.x;
    if (b >= NB) return;
    #pragma unroll
    for (int o = 0; o < 2; o++) {
        const float* f = g_fA + o * NK;
        const float* hs = g_hsum + b * NH;
        float s = 0.f;
        for (int k = 0; k < NH; k++) s += f[k] * hs[k];
        #pragma unroll
        for (int q = 0; q < 4; q++) {
            const float* hq = g_hsum + ((4 * b + q) & 1023) * NH;
            const float* fq = f + 128 + q * 128;
            for (int m = 0; m < NH; m++) s += fq[m] * hq[m];
        }
        out[b * 2 + o] = fc_b[o] + s * (1.f / (float)NT);
    }
}

// ---------------- launch ----------------
extern "C" void kernel_launch(void* const* d_in, const int* in_sizes, int n_in,
                              void* d_out, int out_size) {
    const float* x      = (const float*)d_in[0];
    const float* memory = (const float*)d_in[1];
    const float* rv0    = (const float*)d_in[2];
    const float* W_ih   = (const float*)d_in[3];
    const float* W_hh   = (const float*)d_in[4];
    const float* b_ih   = (const float*)d_in[5];
    const float* b_hh   = (const float*)d_in[6];
    const float* fc_w   = (const float*)d_in[7];
    const float* fc_b   = (const float*)d_in[8];
    float* out = (float*)d_out;

    init_kernel<<<dim3((NB * NH + 255) / 256), 256>>>();
    setup_kernel<<<1, 128>>>(memory, b_ih, b_hh, rv0, W_ih);
    buildA_kernel<<<dim3(514, 5), 128>>>(W_ih, W_hh, fc_w);
    pre_kernel<<<dim3((NT * NB) / 64, NG / 64), 256>>>(x, W_ih);
    for (int t = 0; t < NT; t++) {
        stepmm_kernel<<<dim3(NB / 64, NG / 64, NSPLIT), 256>>>(t);
        lstm_kernel<<<dim3(NB * NH / 256), 256>>>(t);
    }
    final_kernel<<<dim3(4), 256>>>(out, fc_b);
}

// round 6
// speedup vs baseline: 1.9183x; 1.0390x over previous
#include <cuda_runtime.h>

// ---------------- problem constants ----------------
#define NB 1024
#define NT 128
#define ND 256
#define NH 128
#define NG 512
#define NK 640
#define KSPLIT 4
#define KPER (NK / KSPLIT)     // 160
#define NSLAB (KPER / 32)      // 5
#define NCTA 128

typedef unsigned long long ull;
typedef ulonglong2 ull2;

// ---------------- f32x2 packed math ----------------
__device__ __forceinline__ ull ffma2(ull a, ull b, ull c) {
    ull d;
    asm("fma.rn.f32x2 %0, %1, %2, %3;" : "=l"(d) : "l"(a), "l"(b), "l"(c));
    return d;
}
__device__ __forceinline__ float2 unpack2(ull v) {
    float2 r; asm("mov.b64 {%0, %1}, %2;" : "=f"(r.x), "=f"(r.y) : "l"(v)); return r;
}
__device__ __forceinline__ float sig_fast(float x) { return 1.0f / (1.0f + __expf(-x)); }
__device__ __forceinline__ float tanh_fast(float x) { return 2.0f / (1.0f + __expf(-2.0f * x)) - 1.0f; }

__device__ __forceinline__ unsigned smem_u32(const void* p) {
    unsigned r;
    asm("{ .reg .u64 t; cvta.to.shared.u64 t, %1; cvt.u32.u64 %0, t; }" : "=r"(r) : "l"(p));
    return r;
}
#define CP16(dst, src) asm volatile("cp.async.cg.shared.global [%0], [%1], 16;" :: "r"(dst), "l"(src))
#define CP_COMMIT()    asm volatile("cp.async.commit_group;")
#define CP_WAIT1()     asm volatile("cp.async.wait_group 1;")
#define CP_WAIT0()     asm volatile("cp.async.wait_group 0;")

// ---------------- device scratch ----------------
__device__ float g_pre[(size_t)NT * NB * NG];   // [t*NB+b][rr]  (gate-reordered cols)
__device__ float g_Wro[NG * NK];                // row rr=4u+gate, cols [W_hh | A_0..A_3]
__device__ float g_Wxro[NG * ND];               // reordered x-part of W_ih
__device__ float g_part[KSPLIT][(size_t)NB * NG];
__device__ float g_memsm[NH * NH];
__device__ float g_fA[2 * NK];
__device__ float g_h[2][NB * NH];
__device__ float g_c[NB * NH];
__device__ float g_hsum[NB * NH];
__device__ float g_biasro[NG];
__device__ float g_c0ro[NG];
__device__ unsigned g_arrive;
__device__ unsigned g_gen;

// ---------------- grid barrier (sense-reversing) ----------------
__device__ __forceinline__ void grid_barrier() {
    __syncthreads();
    if (threadIdx.x == 0) {
        __threadfence();
        unsigned gen = *(volatile unsigned*)&g_gen;   // MUST read before arriving
        unsigned t = atomicAdd(&g_arrive, 1u);
        if (t == (unsigned)(gridDim.x - 1)) {
            g_arrive = 0;
            __threadfence();
            *(volatile unsigned*)&g_gen = gen + 1;
        } else {
            while (*(volatile unsigned*)&g_gen == gen) { __nanosleep(64); }
        }
        __threadfence();
    }
    __syncthreads();
}

// ---------------- 8x8 f32x2 inner product over one 32-k slab (8 quads) ---------
// A layout: row r (0..127), quad qn at byte  r*128 + ((qn ^ permA(r))<<4), permA(r)=(r^(r>>3))&7
// B layouts give boff[j] with same XOR trick; q<<4 XORed per iteration.
__device__ __forceinline__ void slab_compute(const char* Ab, const char* Bb,
                                             const int aoff[8], const int boff[8],
                                             ull* acc) {
    #pragma unroll
    for (int q = 0; q < 8; q++) {
        ull2 b[8];
        #pragma unroll
        for (int j = 0; j < 8; j++)
            b[j] = *(const ull2*)(Bb + (boff[j] ^ (q << 4)));
        #pragma unroll
        for (int i = 0; i < 8; i++) {
            ull2 a = *(const ull2*)(Ab + (aoff[i] ^ (q << 4)));
            #pragma unroll
            for (int j = 0; j < 8; j++) {
                acc[i * 8 + j] = ffma2(a.x, b[j].x, acc[i * 8 + j]);
                acc[i * 8 + j] = ffma2(a.y, b[j].y, acc[i * 8 + j]);
            }
        }
    }
}

// ---------------- setup: softmax, reordered bias/const0 ----------------
__global__ void setup_kernel(const float* __restrict__ memory,
                             const float* __restrict__ b_ih,
                             const float* __restrict__ b_hh,
                             const float* __restrict__ rv0,
                             const float* __restrict__ W_ih) {
    int tid = threadIdx.x;
    float mx = -1e30f;
    for (int m = 0; m < NH; m++) mx = fmaxf(mx, memory[m * NH + tid]);
    float s = 0.f;
    for (int m = 0; m < NH; m++) s += expf(memory[m * NH + tid] - mx);
    float inv = 1.f / s;
    for (int m = 0; m < NH; m++)
        g_memsm[m * NH + tid] = expf(memory[m * NH + tid] - mx) * inv;

    for (int g = tid; g < NG; g += 128) {
        int u = g & 127, gate = g >> 7;
        int rr = 4 * u + gate;
        g_biasro[rr] = b_ih[g] + b_hh[g];
        float c0 = 0.f;
        const float* w = W_ih + (size_t)g * 768 + 256;
        for (int k = 0; k < 512; k++) c0 += rv0[k] * w[k];
        g_c0ro[rr] = c0;
    }
}

// ---------------- fold mem_sm into weights (reordered rows) ----------------
__global__ void buildA_kernel(const float* __restrict__ W_ih,
                              const float* __restrict__ W_hh,
                              const float* __restrict__ fc_w) {
    int row = blockIdx.x, q = blockIdx.y, j = threadIdx.x;
    if (row < NG) {
        int u = row >> 2, gate = row & 3;
        int go = gate * 128 + u;
        if (q == 0) {
            g_Wro[(size_t)row * NK + j] = W_hh[(size_t)go * NH + j];
        } else {
            const float* w = W_ih + (size_t)go * 768 + 256 + (q - 1) * 128;
            float s = 0.f;
            for (int m = 0; m < NH; m++) s += w[m] * g_memsm[m * NH + j];
            g_Wro[(size_t)row * NK + q * 128 + j] = s;
        }
    } else {
        int o = row - NG;
        if (q == 0) {
            g_fA[o * NK + j] = fc_w[o * NK + j];
        } else {
            const float* w = fc_w + o * NK + 128 + (q - 1) * 128;
            float s = 0.f;
            for (int m = 0; m < NH; m++) s += w[m] * g_memsm[m * NH + j];
            g_fA[o * NK + q * 128 + j] = s;
        }
    }
}

__global__ void buildX_kernel(const float* __restrict__ W_ih) {
    int row = blockIdx.x;   // rr
    int q   = blockIdx.y;   // 0..1
    int j   = threadIdx.x;
    int u = row >> 2, gate = row & 3;
    int go = gate * 128 + u;
    g_Wxro[(size_t)row * ND + q * 128 + j] = W_ih[(size_t)go * 768 + q * 128 + j];
}

// ---------------- pre: [NT*NB,256] x [256,512] -> g_pre (reordered cols) -------
extern __shared__ float4 dynsm[];

__global__ __launch_bounds__(256)
void pre_kernel(const float* __restrict__ x) {
    // smem: 3 stages x (A 1024 quads + B 1024 quads) = 96 KB
    char* smc = (char*)dynsm;
    int r0  = blockIdx.x * 128;   // rows r = t*1024+b (tile spans one t)
    int rr0 = blockIdx.y * 128;
    int tid = threadIdx.x;
    int tx = tid & 15, ty = tid >> 4;

    // issue-side mapping
    int srow = tid >> 1;
    int h4 = (tid & 1) * 4;
    int sperm = (srow ^ (srow >> 3)) & 7;
    int rA = r0 + srow;
    int bA = rA & 1023, tA = rA >> 10;
    const float* xrow = x + ((size_t)bA * NT + tA) * ND;
    const float* wrow = g_Wxro + (size_t)(rr0 + srow) * ND;
    unsigned smem_base = smem_u32(smc);

    #define PRE_ISSUE(s)                                                        \
    {                                                                           \
        unsigned abase = smem_base + ((s) % 3) * 32768u + (unsigned)(srow * 128); \
        unsigned bbase = abase + 16384u;                                        \
        const float* ap = xrow + (s) * 32;                                      \
        const float* bp = wrow + (s) * 32;                                      \
        _Pragma("unroll")                                                       \
        for (int p = 0; p < 4; p++) {                                           \
            int qn = h4 + p;                                                    \
            CP16(abase + ((qn ^ sperm) << 4), ap + qn * 4);                     \
            CP16(bbase + ((qn ^ sperm) << 4), bp + qn * 4);                     \
        }                                                                       \
        CP_COMMIT();                                                            \
    }

    int aoff[8], boff[8];
    #pragma unroll
    for (int i = 0; i < 8; i++) {
        aoff[i] = ((ty * 8 + i) * 128) ^ ((((ty ^ i) & 7)) << 4);
        boff[i] = ((tx * 8 + i) * 128) ^ ((((tx ^ i) & 7)) << 4);
    }

    ull acc[64];
    #pragma unroll
    for (int i = 0; i < 64; i++) acc[i] = 0ull;

    const int NS = ND / 32;   // 8
    PRE_ISSUE(0);
    PRE_ISSUE(1);
    for (int s = 0; s < NS; s++) {
        if (s + 2 < NS) { CP_WAIT1(); } else { CP_WAIT0(); }
        __syncthreads();
        if (s + 2 < NS) PRE_ISSUE(s + 2);
        const char* Ab = smc + (s % 3) * 32768;
        slab_compute(Ab, Ab + 16384, aoff, boff, acc);
        __syncthreads();
    }
    #undef PRE_ISSUE

    int tt = r0 >> 10;
    #pragma unroll
    for (int i = 0; i < 8; i++) {
        int r = r0 + ty * 8 + i;
        float* outp = g_pre + (size_t)r * NG + rr0 + tx * 8;
        #pragma unroll
        for (int h = 0; h < 2; h++) {
            float4 v;
            float2 s0 = unpack2(acc[i * 8 + h * 4 + 0]);
            float2 s1 = unpack2(acc[i * 8 + h * 4 + 1]);
            float2 s2 = unpack2(acc[i * 8 + h * 4 + 2]);
            float2 s3 = unpack2(acc[i * 8 + h * 4 + 3]);
            int rr = rr0 + tx * 8 + h * 4;
            v.x = s0.x + s0.y + g_biasro[rr];
            v.y = s1.x + s1.y + g_biasro[rr + 1];
            v.z = s2.x + s2.y + g_biasro[rr + 2];
            v.w = s3.x + s3.y + g_biasro[rr + 3];
            if (tt == 0) {
                v.x += g_c0ro[rr];     v.y += g_c0ro[rr + 1];
                v.z += g_c0ro[rr + 2]; v.w += g_c0ro[rr + 3];
            }
            *(float4*)(outp + h * 4) = v;
        }
    }
}

// ---------------- persistent recurrence kernel ----------------
__global__ __launch_bounds__(256)
void recur_kernel() {
    // smem: Bres 5120 quads (80KB) + 3 A-stages x 1024 quads (48KB) = 128KB
    char* smc = (char*)dynsm;
    char* Bres = smc;
    char* Ast  = smc + 81920;

    int tid = threadIdx.x;
    int cta = blockIdx.x;
    int sp = cta & 3;
    int tile = cta >> 2;
    int b0  = (tile & 7) << 7;
    int rr0 = (tile >> 3) << 7;
    int tx = tid & 15, ty = tid >> 4;

    // ---- zero h0/c/hsum slice ----
    {
        int idx = cta * 1024 + tid * 4;
        float4 z = make_float4(0.f, 0.f, 0.f, 0.f);
        *(float4*)(g_h[0] + idx) = z;
        *(float4*)(g_c + idx) = z;
        *(float4*)(g_hsum + idx) = z;
    }

    // ---- load resident B tile (128 cols x 160 k) ----
    {
        unsigned bb = smem_u32(Bres);
        for (int idx = tid; idx < 128 * 40; idx += 256) {
            int c = idx / 40, gq = idx % 40;
            int perm = (c ^ (c >> 3)) & 7;
            CP16(bb + (unsigned)((c * 40 + (gq ^ perm)) << 4),
                 g_Wro + (size_t)(rr0 + c) * NK + sp * KPER + gq * 4);
        }
        CP_COMMIT(); CP_WAIT0();
    }
    grid_barrier();

    // ---- per-thread constants ----
    int srow = tid >> 1;            // A fill: row 0..127
    int h4 = (tid & 1) * 4;
    int sperm = (srow ^ (srow >> 3)) & 7;
    int bA = b0 + srow;
    unsigned asm_base = smem_u32(Ast) + (unsigned)(srow * 128);

    int aoff[8], boff[8];
    #pragma unroll
    for (int i = 0; i < 8; i++) {
        aoff[i] = ((ty * 8 + i) * 128) ^ ((((ty ^ i) & 7)) << 4);
        boff[i] = ((tx * 8 + i) * 640) ^ ((((tx ^ i) & 7)) << 4);
    }

    // LSTM-phase mapping
    int lb = cta * 8 + (tid >> 5);
    int u0 = (tid & 31) * 4;

    for (int t = 0; t < NT; t++) {
        const float* __restrict__ Hp = g_h[t & 1];

        #define REC_ISSUE(s)                                                    \
        {                                                                       \
            int k0 = sp * KPER + (s) * 32;                                      \
            int src, col;                                                       \
            if (k0 < 128) { src = bA; col = k0; }                               \
            else { int qd = (k0 - 128) >> 7; src = (4 * bA + qd) & 1023; col = (k0 - 128) & 127; } \
            const float* ap = Hp + src * NH + col;                              \
            unsigned abase = asm_base + ((s) % 3) * 16384u;                     \
            _Pragma("unroll")                                                   \
            for (int p = 0; p < 4; p++) {                                       \
                int qn = h4 + p;                                                \
                CP16(abase + ((qn ^ sperm) << 4), ap + qn * 4);                 \
            }                                                                   \
            CP_COMMIT();                                                        \
        }

        ull acc[64];
        #pragma unroll
        for (int i = 0; i < 64; i++) acc[i] = 0ull;

        REC_ISSUE(0);
        REC_ISSUE(1);
        for (int s = 0; s < NSLAB; s++) {
            if (s + 2 < NSLAB) { CP_WAIT1(); } else { CP_WAIT0(); }
            __syncthreads();
            if (s + 2 < NSLAB) REC_ISSUE(s + 2);
            slab_compute(Ast + (s % 3) * 16384, Bres + s * 128, aoff, boff, acc);
            __syncthreads();
        }
        #undef REC_ISSUE

        // ---- store partials ----
        {
            float* P = g_part[sp];
            #pragma unroll
            for (int i = 0; i < 8; i++) {
                int b = b0 + ty * 8 + i;
                float* outp = P + (size_t)b * NG + rr0 + tx * 8;
                #pragma unroll
                for (int h = 0; h < 2; h++) {
                    float2 s0 = unpack2(acc[i * 8 + h * 4 + 0]);
                    float2 s1 = unpack2(acc[i * 8 + h * 4 + 1]);
                    float2 s2 = unpack2(acc[i * 8 + h * 4 + 2]);
                    float2 s3 = unpack2(acc[i * 8 + h * 4 + 3]);
                    float4 v = make_float4(s0.x + s0.y, s1.x + s1.y,
                                           s2.x + s2.y, s3.x + s3.y);
                    *(float4*)(outp + h * 4) = v;
                }
            }
        }
        grid_barrier();

        // ---- LSTM pointwise: 4 cells per thread ----
        {
            const float4* P0 = (const float4*)(g_part[0] + (size_t)lb * NG + 4 * u0);
            const float4* P1 = (const float4*)(g_part[1] + (size_t)lb * NG + 4 * u0);
            const float4* P2 = (const float4*)(g_part[2] + (size_t)lb * NG + 4 * u0);
            const float4* P3 = (const float4*)(g_part[3] + (size_t)lb * NG + 4 * u0);
            const float4* PR = (const float4*)(g_pre + ((size_t)t * NB + lb) * NG + 4 * u0);
            int cidx = lb * NH + u0;
            float4 cold = *(float4*)(g_c + cidx);
            float4 hs   = *(float4*)(g_hsum + cidx);
            float cn[4], hn[4];
            float co[4] = {cold.x, cold.y, cold.z, cold.w};
            #pragma unroll
            for (int du = 0; du < 4; du++) {
                float4 a = P0[du], b = P1[du], c = P2[du], d = P3[du], p = PR[du];
                float gi = a.x + b.x + c.x + d.x + p.x;
                float gf = a.y + b.y + c.y + d.y + p.y;
                float gg = a.z + b.z + c.z + d.z + p.z;
                float go = a.w + b.w + c.w + d.w + p.w;
                float cv = sig_fast(gf) * co[du] + sig_fast(gi) * tanh_fast(gg);
                cn[du] = cv;
                hn[du] = sig_fast(go) * tanh_fast(cv);
            }
            *(float4*)(g_c + cidx) = make_float4(cn[0], cn[1], cn[2], cn[3]);
            *(float4*)(g_h[(t + 1) & 1] + cidx) = make_float4(hn[0], hn[1], hn[2], hn[3]);
            *(float4*)(g_hsum + cidx) = make_float4(hs.x + hn[0], hs.y + hn[1],
                                                    hs.z + hn[2], hs.w + hn[3]);
        }
        grid_barrier();
    }
}

// ---------------- final ----------------
__global__ void final_kernel(float* __restrict__ out, const float* __restrict__ fc_b) {
    int b = blockIdx.x * blockDim.x + threadIdx.x;
    if (b >= NB) return;
    #pragma unroll
    for (int o = 0; o < 2; o++) {
        const float* f = g_fA + o * NK;
        const float* hs = g_hsum + b * NH;
        float s = 0.f;
        for (int k = 0; k < NH; k++) s += f[k] * hs[k];
        #pragma unroll
        for (int q = 0; q < 4; q++) {
            const float* hq = g_hsum + ((4 * b + q) & 1023) * NH;
            const float* fq = f + 128 + q * 128;
            for (int m = 0; m < NH; m++) s += fq[m] * hq[m];
        }
        out[b * 2 + o] = fc_b[o] + s * (1.f / (float)NT);
    }
}

// ---------------- launch ----------------
extern "C" void kernel_launch(void* const* d_in, const int* in_sizes, int n_in,
                              void* d_out, int out_size) {
    const float* x      = (const float*)d_in[0];
    const float* memory = (const float*)d_in[1];
    const float* rv0    = (const float*)d_in[2];
    const float* W_ih   = (const float*)d_in[3];
    const float* W_hh   = (const float*)d_in[4];
    const float* b_ih   = (const float*)d_in[5];
    const float* b_hh   = (const float*)d_in[6];
    const float* fc_w   = (const float*)d_in[7];
    const float* fc_b   = (const float*)d_in[8];
    float* out = (float*)d_out;

    static bool attr_done = false;
    if (!attr_done) {
        cudaFuncSetAttribute(pre_kernel, cudaFuncAttributeMaxDynamicSharedMemorySize, 98304);
        cudaFuncSetAttribute(recur_kernel, cudaFuncAttributeMaxDynamicSharedMemorySize, 131072);
        attr_done = true;
    }

    setup_kernel<<<1, 128>>>(memory, b_ih, b_hh, rv0, W_ih);
    buildA_kernel<<<dim3(514, 5), 128>>>(W_ih, W_hh, fc_w);
    buildX_kernel<<<dim3(512, 2), 128>>>(W_ih);
    pre_kernel<<<dim3(NT * NB / 128, NG / 128), 256, 98304>>>(x);
    recur_kernel<<<NCTA, 256, 131072>>>();
    final_kernel<<<4, 256>>>(out, fc_b);
}